// round 1
// baseline (speedup 1.0000x reference)
#include <cuda_runtime.h>

typedef unsigned int u32;
typedef unsigned long long u64;
typedef unsigned char u8;

#define NSEG 2621440u      // voxels per sample == template size
#define NSAMP 8
#define SEGS 9             // 8 samples + 1 template segment
#define TPB 256
#define IPT 16
#define TILE 4096          // TPB*IPT
#define TILES 640          // NSEG / TILE (exact)

// Static device scratch (allocation-free rule: __device__ globals)
__device__ u64 g_bufA[(size_t)SEGS * NSEG];
__device__ u64 g_bufB[(size_t)SEGS * NSEG];
__device__ u32 g_hist[(size_t)SEGS * TILES * 256];
__device__ u32 g_base[SEGS * 256];
__device__ float g_tval[NSEG];

// float -> order-preserving u32
__device__ __forceinline__ u32 f2k(float f) {
    u32 u = __float_as_uint(f);
    return u ^ ((u & 0x80000000u) ? 0xFFFFFFFFu : 0x80000000u);
}
// inverse
__device__ __forceinline__ float k2f(u32 u) {
    u ^= ((u & 0x80000000u) ? 0x80000000u : 0xFFFFFFFFu);
    return __uint_as_float(u);
}

// ---------------- pack: (key<<32)|idx ----------------
__global__ void pack_k(const float* __restrict__ x, const float* __restrict__ t) {
    const int seg = blockIdx.y;
    const float* src = (seg < NSAMP) ? (x + (size_t)seg * NSEG) : t;
    u64* dst = g_bufA + (size_t)seg * NSEG;
    for (u32 j = (blockIdx.x * TPB + threadIdx.x) * 4; j < NSEG; j += gridDim.x * TPB * 4) {
        float4 v = *reinterpret_cast<const float4*>(src + j);
        dst[j + 0] = ((u64)f2k(v.x) << 32) | (j + 0);
        dst[j + 1] = ((u64)f2k(v.y) << 32) | (j + 1);
        dst[j + 2] = ((u64)f2k(v.z) << 32) | (j + 2);
        dst[j + 3] = ((u64)f2k(v.w) << 32) | (j + 3);
    }
}

// ---------------- per-tile digit histogram ----------------
template<int SHIFT, bool SRCA>
__global__ void __launch_bounds__(TPB) hist_k() {
    __shared__ u32 h[8][256];
    const u64* __restrict__ in = SRCA ? g_bufA : g_bufB;
    const int t = threadIdx.x;
    const int w = t >> 5;
    const int tile = blockIdx.x, seg = blockIdx.y;
    #pragma unroll
    for (int i = t; i < 8 * 256; i += TPB) (&h[0][0])[i] = 0;
    __syncthreads();
    const size_t base = (size_t)seg * NSEG + (size_t)tile * TILE;
    #pragma unroll
    for (int k = 0; k < IPT; k++) {
        u64 it = in[base + (size_t)k * TPB + t];
        u32 d = (u32)(it >> SHIFT) & 255u;
        atomicAdd(&h[w][d], 1u);
    }
    __syncthreads();
    u32 s = 0;
    #pragma unroll
    for (int w2 = 0; w2 < 8; w2++) s += h[w2][t];
    g_hist[((size_t)seg * TILES + tile) * 256 + t] = s;
}

// ---------------- scan: tile-exclusive prefix per (seg,digit) + digit bases ----------------
__global__ void scan_k() {
    __shared__ u32 sh[256];
    const int d = threadIdx.x, seg = blockIdx.x;
    u32* h = &g_hist[(size_t)seg * TILES * 256];
    u32 run = 0;
    for (int tile = 0; tile < TILES; tile++) {
        u32 c = h[(size_t)tile * 256 + d];
        h[(size_t)tile * 256 + d] = run;
        run += c;
    }
    sh[d] = run;
    __syncthreads();
    // Hillis-Steele inclusive scan over 256 digit totals
    for (int off = 1; off < 256; off <<= 1) {
        u32 v = (d >= off) ? sh[d - off] : 0u;
        __syncthreads();
        sh[d] += v;
        __syncthreads();
    }
    g_base[seg * 256 + d] = sh[d] - run;  // exclusive
}

// ---------------- stable rank + scatter ----------------
// MODE 0: write packed u64 to the other buffer (sorted position).
// MODE 1: fused epilogue: out[idx] = g_tval[sorted_position].
template<int SHIFT, int MODE, bool SRCA>
__global__ void __launch_bounds__(TPB) scatter_k(float* __restrict__ outf, int segOff) {
    __shared__ u8 cnt8[IPT * 8 * 256];   // 32 KB: per (round, warp, digit) counts -> warp prefixes
    __shared__ u32 rb[IPT * 256];        // 16 KB: absolute base per (round, digit)
    const u64* __restrict__ in = SRCA ? g_bufA : g_bufB;
    u64* __restrict__ outp = SRCA ? g_bufB : g_bufA;

    const int t = threadIdx.x;
    const int w = t >> 5;
    const int l = t & 31;
    const u32 lanemask_lt = (1u << l) - 1u;
    const int tile = blockIdx.x;
    const int seg = blockIdx.y + segOff;
    const size_t base = (size_t)seg * NSEG + (size_t)tile * TILE;

    // issue global loads early (striped => element order (k, warp, lane) == ascending index)
    u64 item[IPT];
    #pragma unroll
    for (int k = 0; k < IPT; k++) item[k] = in[base + (size_t)k * TPB + t];

    // digit base for this (seg, tile): digit-global base + earlier-tile count
    u32 run = g_base[seg * 256 + t] + g_hist[((size_t)seg * TILES + tile) * 256 + t];

    // zero counters
    u32* c32 = reinterpret_cast<u32*>(cnt8);
    #pragma unroll
    for (int i = 0; i < (IPT * 8 * 256 / 4) / TPB; i++) c32[i * TPB + t] = 0;
    __syncthreads();

    // phase 4: warp match ranking, leader records per-(round,warp,digit) count
    u32 lr0 = 0, lr1 = 0, lr2 = 0, lr3 = 0;
    #pragma unroll
    for (int k = 0; k < IPT; k++) {
        u32 d = (u32)(item[k] >> SHIFT) & 255u;
        u32 mask = __match_any_sync(0xFFFFFFFFu, d);
        u32 r = __popc(mask & lanemask_lt);
        if (r == 0) cnt8[(k * 8 + w) * 256 + d] = (u8)__popc(mask);
        if (k < 4)       lr0 |= r << (8 * k);
        else if (k < 8)  lr1 |= r << (8 * (k - 4));
        else if (k < 12) lr2 |= r << (8 * (k - 8));
        else             lr3 |= r << (8 * (k - 12));
    }
    __syncthreads();

    // phase 6: thread t owns digit t; serial prefix over 128 (round, warp) cells
    #pragma unroll
    for (int k = 0; k < IPT; k++) {
        rb[k * 256 + t] = run;
        u32 rs = run;
        #pragma unroll
        for (int w2 = 0; w2 < 8; w2++) {
            u32 i = (u32)(k * 8 + w2) * 256 + t;
            u32 c = cnt8[i];
            cnt8[i] = (u8)(run - rs);   // warp prefix relative to round start (<= 224)
            run += c;
        }
    }
    __syncthreads();

    // phase 8: compute final positions, write
    #pragma unroll
    for (int k = 0; k < IPT; k++) {
        u32 d = (u32)(item[k] >> SHIFT) & 255u;
        u32 r;
        if (k < 4)       r = (lr0 >> (8 * k)) & 255u;
        else if (k < 8)  r = (lr1 >> (8 * (k - 4))) & 255u;
        else if (k < 12) r = (lr2 >> (8 * (k - 8))) & 255u;
        else             r = (lr3 >> (8 * (k - 12))) & 255u;
        u32 pos = rb[k * 256 + d] + (u32)cnt8[(k * 8 + w) * 256 + d] + r;
        if (MODE == 0) {
            outp[(size_t)seg * NSEG + pos] = item[k];
        } else {
            u32 idx = (u32)item[k];
            outf[(size_t)seg * NSEG + idx] = g_tval[pos];
        }
    }
}

// ---------------- template sorted values ----------------
__global__ void tval_k() {
    for (u32 j = blockIdx.x * TPB + threadIdx.x; j < NSEG; j += gridDim.x * TPB) {
        u32 u = (u32)(g_bufA[(size_t)NSAMP * NSEG + j] >> 32);
        g_tval[j] = k2f(u);
    }
}

extern "C" void kernel_launch(void* const* d_in, const int* in_sizes, int n_in,
                              void* d_out, int out_size) {
    const float* x  = (const float*)d_in[0];
    const float* bv = (const float*)d_in[1];
    float* out = (float*)d_out;

    dim3 g9(TILES, SEGS);
    dim3 g8(TILES, NSAMP);
    dim3 g1(TILES, 1);

    pack_k<<<dim3(TILES, SEGS), TPB>>>(x, bv);

    // pass 0: key byte 0 (bits 32..39), A -> B
    hist_k<32, true><<<g9, TPB>>>();
    scan_k<<<SEGS, 256>>>();
    scatter_k<32, 0, true><<<g9, TPB>>>(nullptr, 0);

    // pass 1: B -> A
    hist_k<40, false><<<g9, TPB>>>();
    scan_k<<<SEGS, 256>>>();
    scatter_k<40, 0, false><<<g9, TPB>>>(nullptr, 0);

    // pass 2: A -> B
    hist_k<48, true><<<g9, TPB>>>();
    scan_k<<<SEGS, 256>>>();
    scatter_k<48, 0, true><<<g9, TPB>>>(nullptr, 0);

    // pass 3: hist/scan for all segments on B
    hist_k<56, false><<<g9, TPB>>>();
    scan_k<<<SEGS, 256>>>();
    // template segment first: B -> A (fully sorted template in bufA seg 8)
    scatter_k<56, 0, false><<<g1, TPB>>>(nullptr, NSAMP);
    // materialize sorted template values
    tval_k<<<2560, TPB>>>();
    // fused final pass for the 8 samples: out[idx] = t_sorted[rank]
    scatter_k<56, 1, false><<<g8, TPB>>>(out, 0);
}